// round 1
// baseline (speedup 1.0000x reference)
#include <cuda_runtime.h>
#include <math.h>
#include <float.h>

#define TT   4096        // tokens
#define HD   1024        // hidden
#define EDN  8           // dyn experts
#define NE   9           // total experts (8 dyn + 1 shared)
#define IDY  512         // dyn intermediate
#define IFX  2048        // shared intermediate
#define CAPV 640         // capacity = ceil(4096/8*1.25)
#define TOPK 4
#define TOPP 0.75f
#define JEPS2 0.2f       // 2*jitter_eps

// ----------------- device scratch (static, no allocations) -----------------
__device__ float d_logits[TT * NE];
__device__ int   d_sel[TT * TOPK];
__device__ float d_rw[TT * TOPK];
__device__ int   d_mask[TT * EDN];
__device__ int   d_kept[TT * EDN];
__device__ int   d_counts[EDN];
__device__ int   d_etok[EDN * CAPV];
__device__ int   d_tokpos[TT * TOPK];
__device__ int   d_toke[TT * TOPK];
__device__ float d_tokw[TT * TOPK];
__device__ float d_wsh[TT];
__device__ float d_xe[(size_t)EDN * CAPV * HD];
__device__ float d_gbuf[(size_t)EDN * CAPV * IDY];
__device__ float d_ubuf[(size_t)EDN * CAPV * IDY];
__device__ float d_hbuf[(size_t)EDN * CAPV * IDY];
__device__ float d_ybuf[(size_t)EDN * CAPV * HD];
__device__ float d_gs[(size_t)TT * IFX];
__device__ float d_us[(size_t)TT * IFX];
__device__ float d_hs[(size_t)TT * IFX];

// ----------------- K1: router logits (T x 9), warp per (t,e) ---------------
__global__ __launch_bounds__(256) void logits_kernel(
    const float* __restrict__ x, const float* __restrict__ gw)
{
    int widx = blockIdx.x * 8 + (threadIdx.x >> 5);
    if (widx >= TT * NE) return;
    int t = widx / NE, e = widx - t * NE;
    int lane = threadIdx.x & 31;
    const float4* xr = (const float4*)(x + (size_t)t * HD);
    const float4* wr = (const float4*)(gw + (size_t)e * HD);
    float s = 0.f;
#pragma unroll
    for (int i = 0; i < HD / 128; i++) {
        float4 a = xr[lane + i * 32];
        float4 b = wr[lane + i * 32];
        s += a.x * b.x + a.y * b.y + a.z * b.z + a.w * b.w;
    }
#pragma unroll
    for (int o = 16; o; o >>= 1) s += __shfl_xor_sync(0xffffffffu, s, o);
    if (!lane) d_logits[widx] = s;
}

// ----------------- K2: per-token routing (top-p + sparse mixer) ------------
__global__ void routing_kernel()
{
    int t = blockIdx.x * blockDim.x + threadIdx.x;
    if (t >= TT) return;

    float s[EDN];
#pragma unroll
    for (int e = 0; e < EDN; e++) s[e] = d_logits[t * NE + e];

    // top-p: softmax probs, sort desc, count csum < TOPP
    float m = s[0];
#pragma unroll
    for (int e = 1; e < EDN; e++) m = fmaxf(m, s[e]);
    float p[EDN]; float den = 0.f;
#pragma unroll
    for (int e = 0; e < EDN; e++) { p[e] = expf(s[e] - m); den += p[e]; }
#pragma unroll
    for (int e = 0; e < EDN; e++) p[e] /= den;
    float sp[EDN];
#pragma unroll
    for (int e = 0; e < EDN; e++) sp[e] = p[e];
    for (int i = 1; i < EDN; i++) {           // insertion sort, descending
        float v = sp[i]; int j = i - 1;
        while (j >= 0 && sp[j] < v) { sp[j + 1] = sp[j]; j--; }
        sp[j + 1] = v;
    }
    float c = 0.f; int cnt = 0;
#pragma unroll
    for (int e = 0; e < EDN; e++) { c += sp[e]; if (c < TOPP) cnt++; }
    int dyn_k = min(cnt + 1, TOPK);

    // sparse mixer
    float masked[EDN];
#pragma unroll
    for (int e = 0; e < EDN; e++) masked[e] = s[e];
    float mult[TOPK]; int sel[TOPK];
    for (int k = 0; k < TOPK; k++) {
        float thr = masked[0]; int sl = 0;
        for (int e = 1; e < EDN; e++)
            if (masked[e] > thr) { thr = masked[e]; sl = e; }
        bool keep[EDN];
        float gm = -INFINITY;
        for (int e = 0; e < EDN; e++) {
            float fac = fmaxf(fabsf(s[e]), fabsf(thr));
            float jm = (thr - s[e]) / fac;       // NaN>x is false, matches JAX
            keep[e] = !(jm > JEPS2);
            if (keep[e]) gm = fmaxf(gm, masked[e]);
        }
        float d2 = 0.f;
        for (int e = 0; e < EDN; e++)
            if (keep[e]) d2 += expf(masked[e] - gm);  // exp(-inf)=0 for used slots
        mult[k] = expf(thr - gm) / d2;
        sel[k] = sl;
        masked[sl] = -INFINITY;
    }
    float rsum = 0.f;
#pragma unroll
    for (int k = 0; k < TOPK; k++) {
        if (k >= dyn_k) mult[k] = 0.f;
        rsum += mult[k];
    }
    int mk[EDN];
#pragma unroll
    for (int e = 0; e < EDN; e++) mk[e] = 0;
#pragma unroll
    for (int k = 0; k < TOPK; k++) {
        float r = mult[k] / rsum;
        d_rw[t * TOPK + k] = r;
        d_sel[t * TOPK + k] = sel[k];
        if (mult[k] > 0.f) mk[sel[k]] = 1;
    }
#pragma unroll
    for (int e = 0; e < EDN; e++) d_mask[t * EDN + e] = mk[e];
}

// ----------------- K3: capacity scan (token-order cumsum per expert) -------
__global__ void scan_kernel()
{
    int e = blockIdx.x;
    __shared__ int sd[1024];
    int carry = 0;
    for (int cc = 0; cc < TT / 1024; cc++) {
        int t = cc * 1024 + threadIdx.x;
        int v = d_mask[t * EDN + e];
        sd[threadIdx.x] = v;
        __syncthreads();
        for (int off = 1; off < 1024; off <<= 1) {
            int add = (threadIdx.x >= off) ? sd[threadIdx.x - off] : 0;
            __syncthreads();
            sd[threadIdx.x] += add;
            __syncthreads();
        }
        int incl = sd[threadIdx.x] + carry;
        d_kept[t * EDN + e] = (v && incl <= CAPV) ? 1 : 0;
        carry += sd[1023];
        __syncthreads();
    }
}

__global__ void init_counts_kernel()
{
    if (threadIdx.x < EDN) d_counts[threadIdx.x] = 0;
}

// ----------------- K4: masked softmax over 9 experts + compaction ----------
__global__ void finalize_kernel()
{
    int t = blockIdx.x * blockDim.x + threadIdx.x;
    if (t >= TT) return;
    float l[NE];
#pragma unroll
    for (int i = 0; i < NE; i++) l[i] = d_logits[t * NE + i];
    int km[EDN];
#pragma unroll
    for (int e = 0; e < EDN; e++) km[e] = d_kept[t * EDN + e];

    float m = l[EDN];                       // shared always unmasked
#pragma unroll
    for (int e = 0; e < EDN; e++) if (km[e]) m = fmaxf(m, l[e]);
    float den = 0.f, dynsum = 0.f;
#pragma unroll
    for (int e = 0; e < EDN; e++)
        if (km[e]) { float ex = expf(l[e] - m); den += ex; dynsum += ex; }
    float exsh = expf(l[EDN] - m);
    den += exsh;
    d_wsh[t] = exsh / den;
    float sumdyn = dynsum / den;

#pragma unroll
    for (int k = 0; k < TOPK; k++) {
        float r = d_rw[t * TOPK + k];
        int e = d_sel[t * TOPK + k];
        int pos = -1;
        if (r > 0.f && km[e]) {
            pos = atomicAdd(&d_counts[e], 1);
            d_etok[e * CAPV + pos] = t;
            d_toke[t * TOPK + k] = e;
            d_tokw[t * TOPK + k] = r * sumdyn;
        }
        d_tokpos[t * TOPK + k] = pos;
    }
}

// ----------------- K5: gather x rows per expert (zero-pad to CAPV) ---------
__global__ __launch_bounds__(256) void gather_kernel(const float* __restrict__ x)
{
    int b = blockIdx.x;
    int e = b / CAPV, i = b - e * CAPV;
    int c = threadIdx.x;   // 256 threads * float4 = 1024 floats
    float4* dst = (float4*)(d_xe + ((size_t)e * CAPV + i) * HD);
    if (i < d_counts[e]) {
        int t = d_etok[e * CAPV + i];
        dst[c] = ((const float4*)(x + (size_t)t * HD))[c];
    } else {
        dst[c] = make_float4(0.f, 0.f, 0.f, 0.f);
    }
}

// ----------------- tiled SGEMM: C[M,N] = A[M,K] @ B[N,K]^T -----------------
// 128x128 block tile, BK=8, 256 threads, 8x8 per-thread tile.
// All M,N,K here are multiples of 128/128/8 so no edge guards needed.
// mode=1: C[r,:] = rowscale[r] * acc (used for shared-expert down proj).
__global__ __launch_bounds__(256, 2) void gemm_kernel(
    const float* __restrict__ A, const float* __restrict__ B, float* __restrict__ C,
    int K, int N, size_t sA, size_t sB, size_t sC,
    int mode, const float* __restrict__ rs)
{
    int e = blockIdx.z;
    A += (size_t)e * sA; B += (size_t)e * sB; C += (size_t)e * sC;

    __shared__ float As[8][128];
    __shared__ float Bs[8][128];

    int tid = threadIdx.x;
    int ty = tid >> 4, tx = tid & 15;
    int rowBase = blockIdx.y * 128, colBase = blockIdx.x * 128;
    int lr = tid >> 1, lk = (tid & 1) * 4;
    const float* Ap = A + (size_t)(rowBase + lr) * K + lk;
    const float* Bp = B + (size_t)(colBase + lr) * K + lk;

    float acc[8][8];
#pragma unroll
    for (int i = 0; i < 8; i++)
#pragma unroll
        for (int j = 0; j < 8; j++) acc[i][j] = 0.f;

    for (int k0 = 0; k0 < K; k0 += 8) {
        float4 av = *(const float4*)(Ap + k0);
        float4 bv = *(const float4*)(Bp + k0);
        __syncthreads();
        As[lk + 0][lr] = av.x; As[lk + 1][lr] = av.y;
        As[lk + 2][lr] = av.z; As[lk + 3][lr] = av.w;
        Bs[lk + 0][lr] = bv.x; Bs[lk + 1][lr] = bv.y;
        Bs[lk + 2][lr] = bv.z; Bs[lk + 3][lr] = bv.w;
        __syncthreads();
#pragma unroll
        for (int k = 0; k < 8; k++) {
            float a[8], b[8];
#pragma unroll
            for (int i = 0; i < 8; i++) a[i] = As[k][ty * 8 + i];
#pragma unroll
            for (int j = 0; j < 8; j++) b[j] = Bs[k][tx * 8 + j];
#pragma unroll
            for (int i = 0; i < 8; i++)
#pragma unroll
                for (int j = 0; j < 8; j++) acc[i][j] += a[i] * b[j];
        }
    }

#pragma unroll
    for (int i = 0; i < 8; i++) {
        int r = rowBase + ty * 8 + i;
        float sc = mode ? rs[r] : 1.f;
        float* Cr = C + (size_t)r * N + colBase + tx * 8;
        float4 v0, v1;
        v0.x = acc[i][0] * sc; v0.y = acc[i][1] * sc;
        v0.z = acc[i][2] * sc; v0.w = acc[i][3] * sc;
        v1.x = acc[i][4] * sc; v1.y = acc[i][5] * sc;
        v1.z = acc[i][6] * sc; v1.w = acc[i][7] * sc;
        *(float4*)Cr = v0;
        *(float4*)(Cr + 4) = v1;
    }
}

// ----------------- silu(g)*u elementwise -----------------------------------
__global__ __launch_bounds__(256) void silu_mul_kernel(
    const float* __restrict__ g, const float* __restrict__ u,
    float* __restrict__ h, int n4)
{
    int i = blockIdx.x * blockDim.x + threadIdx.x;
    if (i >= n4) return;
    float4 gv = ((const float4*)g)[i];
    float4 uv = ((const float4*)u)[i];
    float4 r;
    r.x = gv.x / (1.f + expf(-gv.x)) * uv.x;
    r.y = gv.y / (1.f + expf(-gv.y)) * uv.y;
    r.z = gv.z / (1.f + expf(-gv.z)) * uv.z;
    r.w = gv.w / (1.f + expf(-gv.w)) * uv.w;
    ((float4*)h)[i] = r;
}

// ----------------- combine dyn expert outputs into out ---------------------
__global__ __launch_bounds__(256) void combine_kernel(float* __restrict__ out)
{
    int t = blockIdx.x;
    int c = threadIdx.x;   // 256 * float4 = 1024
    float4 acc = ((float4*)(out + (size_t)t * HD))[c];
#pragma unroll
    for (int k = 0; k < TOPK; k++) {
        int pos = d_tokpos[t * TOPK + k];
        if (pos >= 0) {
            int e = d_toke[t * TOPK + k];
            float w = d_tokw[t * TOPK + k];
            float4 v = ((const float4*)(d_ybuf + ((size_t)e * CAPV + pos) * HD))[c];
            acc.x += w * v.x; acc.y += w * v.y;
            acc.z += w * v.z; acc.w += w * v.w;
        }
    }
    ((float4*)(out + (size_t)t * HD))[c] = acc;
}

// ----------------- host launcher -------------------------------------------
extern "C" void kernel_launch(void* const* d_in, const int* in_sizes, int n_in,
                              void* d_out, int out_size)
{
    const float* x   = (const float*)d_in[0];
    const float* gw  = (const float*)d_in[1];
    const float* dgw = (const float*)d_in[2];
    const float* duw = (const float*)d_in[3];
    const float* ddw = (const float*)d_in[4];
    const float* sgw = (const float*)d_in[5];
    const float* suw = (const float*)d_in[6];
    const float* sdw = (const float*)d_in[7];
    float* out = (float*)d_out;

    float *p_xe, *p_g, *p_u, *p_h, *p_y, *p_gs, *p_us, *p_hs, *p_wsh;
    cudaGetSymbolAddress((void**)&p_xe, d_xe);
    cudaGetSymbolAddress((void**)&p_g, d_gbuf);
    cudaGetSymbolAddress((void**)&p_u, d_ubuf);
    cudaGetSymbolAddress((void**)&p_h, d_hbuf);
    cudaGetSymbolAddress((void**)&p_y, d_ybuf);
    cudaGetSymbolAddress((void**)&p_gs, d_gs);
    cudaGetSymbolAddress((void**)&p_us, d_us);
    cudaGetSymbolAddress((void**)&p_hs, d_hs);
    cudaGetSymbolAddress((void**)&p_wsh, d_wsh);

    // routing
    logits_kernel<<<(TT * NE + 7) / 8, 256>>>(x, gw);
    routing_kernel<<<(TT + 255) / 256, 256>>>();
    scan_kernel<<<EDN, 1024>>>();
    init_counts_kernel<<<1, 32>>>();
    finalize_kernel<<<(TT + 255) / 256, 256>>>();
    gather_kernel<<<EDN * CAPV, 256>>>(x);

    // dyn experts: G/U = Xe @ W^T, H = silu(G)*U, Y = H @ Wd^T
    dim3 g1(IDY / 128, CAPV / 128, EDN);
    gemm_kernel<<<g1, 256>>>(p_xe, dgw, p_g, HD, IDY,
                             (size_t)CAPV * HD, (size_t)IDY * HD, (size_t)CAPV * IDY,
                             0, nullptr);
    gemm_kernel<<<g1, 256>>>(p_xe, duw, p_u, HD, IDY,
                             (size_t)CAPV * HD, (size_t)IDY * HD, (size_t)CAPV * IDY,
                             0, nullptr);
    int n4d = EDN * CAPV * IDY / 4;
    silu_mul_kernel<<<(n4d + 255) / 256, 256>>>(p_g, p_u, p_h, n4d);
    dim3 g2(HD / 128, CAPV / 128, EDN);
    gemm_kernel<<<g2, 256>>>(p_h, ddw, p_y, IDY, HD,
                             (size_t)CAPV * IDY, (size_t)HD * IDY, (size_t)CAPV * HD,
                             0, nullptr);

    // shared expert: dense over all tokens; down proj scaled by gw[:,8] and
    // written (not added) to out — covers every output element.
    dim3 g3(IFX / 128, TT / 128, 1);
    gemm_kernel<<<g3, 256>>>(x, sgw, p_gs, HD, IFX, 0, 0, 0, 0, nullptr);
    gemm_kernel<<<g3, 256>>>(x, suw, p_us, HD, IFX, 0, 0, 0, 0, nullptr);
    int n4s = TT * IFX / 4;
    silu_mul_kernel<<<(n4s + 255) / 256, 256>>>(p_gs, p_us, p_hs, n4s);
    dim3 g4(HD / 128, TT / 128, 1);
    gemm_kernel<<<g4, 256>>>(p_hs, sdw, out, IFX, HD, 0, 0, 0, 1, p_wsh);

    // add dyn contributions
    combine_kernel<<<TT, 256>>>(out);
}

// round 3
// speedup vs baseline: 3.6349x; 3.6349x over previous
#include <cuda_runtime.h>
#include <math.h>
#include <float.h>
#include <stdint.h>

#define TT   4096
#define HD   1024
#define EDN  8
#define NE   9
#define IDY  512
#define IFX  2048
#define CAPV 640
#define TOPK 4
#define TOPP 0.75f
#define JEPS2 0.2f

// ---- mma.sync tf32 GEMM tiling ----
#define BM   128
#define BN   128
#define BK   32
#define BKP  36                                // padded row (floats)
#define NSTG 4
#define STAGE_FLOATS ((BM + BN) * BKP)         // 9216
#define GEMM_SMEM (NSTG * STAGE_FLOATS * 4)    // 147456 B

__device__ __forceinline__ uint32_t smem_u32(const void* p) {
    uint32_t a;
    asm("{ .reg .u64 t; cvta.to.shared.u64 t, %1; cvt.u32.u64 %0, t; }" : "=r"(a) : "l"(p));
    return a;
}
__device__ __forceinline__ void cp_async16(uint32_t dst, const void* src) {
    asm volatile("cp.async.cg.shared.global [%0], [%1], 16;" :: "r"(dst), "l"(src));
}
template<int N> __device__ __forceinline__ void cp_wait() {
    asm volatile("cp.async.wait_group %0;" :: "n"(N) : "memory");
}
__device__ __forceinline__ float rna_tf32(float x) {
    uint32_t u;
    asm("cvt.rna.tf32.f32 %0, %1;" : "=r"(u) : "f"(x));
    return __uint_as_float(u);
}

// ----------------- device scratch (static, no allocations) -----------------
__device__ float d_logits[TT * NE];
__device__ int   d_sel[TT * TOPK];
__device__ float d_rw[TT * TOPK];
__device__ int   d_mask[TT * EDN];
__device__ int   d_kept[TT * EDN];
__device__ int   d_counts[EDN];
__device__ int   d_etok[EDN * CAPV];
__device__ int   d_tokpos[TT * TOPK];
__device__ int   d_toke[TT * TOPK];
__device__ float d_tokw[TT * TOPK];
__device__ float d_wsh[TT];
__device__ float d_xe[(size_t)EDN * CAPV * HD];
__device__ float d_gbuf[(size_t)EDN * CAPV * IDY];
__device__ float d_ubuf[(size_t)EDN * CAPV * IDY];
__device__ float d_hbuf[(size_t)EDN * CAPV * IDY];
__device__ float d_ybuf[(size_t)EDN * CAPV * HD];
__device__ float d_gs[(size_t)TT * IFX];
__device__ float d_us[(size_t)TT * IFX];
__device__ float d_hs[(size_t)TT * IFX];
// tf32-rounded copies
__device__ float d_xr[(size_t)TT * HD];
__device__ float d_dgw_r[(size_t)EDN * IDY * HD];
__device__ float d_duw_r[(size_t)EDN * IDY * HD];
__device__ float d_ddw_r[(size_t)EDN * HD * IDY];
__device__ float d_sgw_r[(size_t)IFX * HD];
__device__ float d_suw_r[(size_t)IFX * HD];
__device__ float d_sdw_r[(size_t)HD * IFX];

// ----------------- K1: router logits ---------------------------------------
__global__ __launch_bounds__(256) void logits_kernel(
    const float* __restrict__ x, const float* __restrict__ gw)
{
    int widx = blockIdx.x * 8 + (threadIdx.x >> 5);
    if (widx >= TT * NE) return;
    int t = widx / NE, e = widx - t * NE;
    int lane = threadIdx.x & 31;
    const float4* xr = (const float4*)(x + (size_t)t * HD);
    const float4* wr = (const float4*)(gw + (size_t)e * HD);
    float s = 0.f;
#pragma unroll
    for (int i = 0; i < HD / 128; i++) {
        float4 a = xr[lane + i * 32];
        float4 b = wr[lane + i * 32];
        s += a.x * b.x + a.y * b.y + a.z * b.z + a.w * b.w;
    }
#pragma unroll
    for (int o = 16; o; o >>= 1) s += __shfl_xor_sync(0xffffffffu, s, o);
    if (!lane) d_logits[widx] = s;
}

// ----------------- K2: per-token routing ------------------------------------
__global__ void routing_kernel()
{
    int t = blockIdx.x * blockDim.x + threadIdx.x;
    if (t >= TT) return;

    float s[EDN];
#pragma unroll
    for (int e = 0; e < EDN; e++) s[e] = d_logits[t * NE + e];

    float m = s[0];
#pragma unroll
    for (int e = 1; e < EDN; e++) m = fmaxf(m, s[e]);
    float p[EDN]; float den = 0.f;
#pragma unroll
    for (int e = 0; e < EDN; e++) { p[e] = expf(s[e] - m); den += p[e]; }
#pragma unroll
    for (int e = 0; e < EDN; e++) p[e] /= den;
    float sp[EDN];
#pragma unroll
    for (int e = 0; e < EDN; e++) sp[e] = p[e];
    for (int i = 1; i < EDN; i++) {
        float v = sp[i]; int j = i - 1;
        while (j >= 0 && sp[j] < v) { sp[j + 1] = sp[j]; j--; }
        sp[j + 1] = v;
    }
    float c = 0.f; int cnt = 0;
#pragma unroll
    for (int e = 0; e < EDN; e++) { c += sp[e]; if (c < TOPP) cnt++; }
    int dyn_k = min(cnt + 1, TOPK);

    float masked[EDN];
#pragma unroll
    for (int e = 0; e < EDN; e++) masked[e] = s[e];
    float mult[TOPK]; int sel[TOPK];
    for (int k = 0; k < TOPK; k++) {
        float thr = masked[0]; int sl = 0;
        for (int e = 1; e < EDN; e++)
            if (masked[e] > thr) { thr = masked[e]; sl = e; }
        bool keep[EDN];
        float gm = -INFINITY;
        for (int e = 0; e < EDN; e++) {
            float fac = fmaxf(fabsf(s[e]), fabsf(thr));
            float jm = (thr - s[e]) / fac;
            keep[e] = !(jm > JEPS2);
            if (keep[e]) gm = fmaxf(gm, masked[e]);
        }
        float d2 = 0.f;
        for (int e = 0; e < EDN; e++)
            if (keep[e]) d2 += expf(masked[e] - gm);
        mult[k] = expf(thr - gm) / d2;
        sel[k] = sl;
        masked[sl] = -INFINITY;
    }
    float rsum = 0.f;
#pragma unroll
    for (int k = 0; k < TOPK; k++) {
        if (k >= dyn_k) mult[k] = 0.f;
        rsum += mult[k];
    }
    int mk[EDN];
#pragma unroll
    for (int e = 0; e < EDN; e++) mk[e] = 0;
#pragma unroll
    for (int k = 0; k < TOPK; k++) {
        float r = mult[k] / rsum;
        d_rw[t * TOPK + k] = r;
        d_sel[t * TOPK + k] = sel[k];
        if (mult[k] > 0.f) mk[sel[k]] = 1;
    }
#pragma unroll
    for (int e = 0; e < EDN; e++) d_mask[t * EDN + e] = mk[e];
}

// ----------------- K3: capacity scan ----------------------------------------
__global__ void scan_kernel()
{
    int e = blockIdx.x;
    __shared__ int sd[1024];
    int carry = 0;
    for (int cc = 0; cc < TT / 1024; cc++) {
        int t = cc * 1024 + threadIdx.x;
        int v = d_mask[t * EDN + e];
        sd[threadIdx.x] = v;
        __syncthreads();
        for (int off = 1; off < 1024; off <<= 1) {
            int add = (threadIdx.x >= off) ? sd[threadIdx.x - off] : 0;
            __syncthreads();
            sd[threadIdx.x] += add;
            __syncthreads();
        }
        int incl = sd[threadIdx.x] + carry;
        d_kept[t * EDN + e] = (v && incl <= CAPV) ? 1 : 0;
        carry += sd[1023];
        __syncthreads();
    }
}

__global__ void init_counts_kernel()
{
    if (threadIdx.x < EDN) d_counts[threadIdx.x] = 0;
}

// ----------------- K4: masked softmax + compaction --------------------------
__global__ void finalize_kernel()
{
    int t = blockIdx.x * blockDim.x + threadIdx.x;
    if (t >= TT) return;
    float l[NE];
#pragma unroll
    for (int i = 0; i < NE; i++) l[i] = d_logits[t * NE + i];
    int km[EDN];
#pragma unroll
    for (int e = 0; e < EDN; e++) km[e] = d_kept[t * EDN + e];

    float m = l[EDN];
#pragma unroll
    for (int e = 0; e < EDN; e++) if (km[e]) m = fmaxf(m, l[e]);
    float den = 0.f, dynsum = 0.f;
#pragma unroll
    for (int e = 0; e < EDN; e++)
        if (km[e]) { float ex = expf(l[e] - m); den += ex; dynsum += ex; }
    float exsh = expf(l[EDN] - m);
    den += exsh;
    d_wsh[t] = exsh / den;
    float sumdyn = dynsum / den;

#pragma unroll
    for (int k = 0; k < TOPK; k++) {
        float r = d_rw[t * TOPK + k];
        int e = d_sel[t * TOPK + k];
        int pos = -1;
        if (r > 0.f && km[e]) {
            pos = atomicAdd(&d_counts[e], 1);
            d_etok[e * CAPV + pos] = t;
            d_toke[t * TOPK + k] = e;
            d_tokw[t * TOPK + k] = r * sumdyn;
        }
        d_tokpos[t * TOPK + k] = pos;
    }
}

// ----------------- K5: gather x rows per expert (tf32-rounded) --------------
__global__ __launch_bounds__(256) void gather_kernel(const float* __restrict__ x)
{
    int b = blockIdx.x;
    int e = b / CAPV, i = b - e * CAPV;
    int c = threadIdx.x;
    float4* dst = (float4*)(d_xe + ((size_t)e * CAPV + i) * HD);
    if (i < d_counts[e]) {
        int t = d_etok[e * CAPV + i];
        float4 v = ((const float4*)(x + (size_t)t * HD))[c];
        v.x = rna_tf32(v.x); v.y = rna_tf32(v.y);
        v.z = rna_tf32(v.z); v.w = rna_tf32(v.w);
        dst[c] = v;
    } else {
        dst[c] = make_float4(0.f, 0.f, 0.f, 0.f);
    }
}

// ----------------- round-to-tf32 prepass ------------------------------------
__global__ __launch_bounds__(256) void round_kernel(
    const float4* __restrict__ in, float4* __restrict__ out, int n4)
{
    int i = blockIdx.x * blockDim.x + threadIdx.x;
    if (i >= n4) return;
    float4 v = in[i];
    v.x = rna_tf32(v.x); v.y = rna_tf32(v.y);
    v.z = rna_tf32(v.z); v.w = rna_tf32(v.w);
    out[i] = v;
}

// ----------------- mma.sync tf32 GEMM: C[M,N] = A[M,K] @ B[N,K]^T -----------
// 128x128x32 CTA tile, 8 warps (2x4), warp tile 64x32, m16n8k8 tf32 MMA,
// 4-stage cp.async pipeline. z < zSplit -> (Ba,Ca), else (Bb,Cb).
// mode=1: scale row r of C by rs[r].
__global__ __launch_bounds__(256, 1) void tf32_gemm_kernel(
    const float* __restrict__ A,
    const float* __restrict__ Ba, const float* __restrict__ Bb,
    float* __restrict__ Ca, float* __restrict__ Cb,
    int K, int N, size_t strA, size_t strB, size_t strC,
    int zSplit, int mode, const float* __restrict__ rs)
{
    extern __shared__ float smem[];
    int tid = threadIdx.x;
    int w = tid >> 5, lane = tid & 31;
    int wm = w >> 2, wn = w & 3;          // 2 x 4 warp grid
    int grp = lane >> 2, tig = lane & 3;  // mma fragment coords

    int z = blockIdx.z;
    const float* Bp; float* Cp; int e;
    if (z < zSplit) { e = z; Bp = Ba; Cp = Ca; }
    else            { e = z - zSplit; Bp = Bb; Cp = Cb; }
    const float* Ap = A + (size_t)e * strA + (size_t)blockIdx.y * BM * K;
    Bp += (size_t)e * strB + (size_t)blockIdx.x * BN * K;
    Cp += (size_t)e * strC;

    float acc[4][4][4] = {};
    int KT = K / BK;

    // prologue: stages 0..NSTG-2
#pragma unroll
    for (int pt = 0; pt < NSTG - 1; pt++) {
        float* dstA = smem + pt * STAGE_FLOATS;
        float* dstB = dstA + BM * BKP;
#pragma unroll
        for (int i = 0; i < 4; i++) {
            int idx = tid + i * 256, row = idx >> 3, c = idx & 7;
            cp_async16(smem_u32(dstA + row * BKP + c * 4),
                       Ap + (size_t)row * K + pt * BK + c * 4);
        }
#pragma unroll
        for (int i = 0; i < 4; i++) {
            int idx = tid + i * 256, row = idx >> 3, c = idx & 7;
            cp_async16(smem_u32(dstB + row * BKP + c * 4),
                       Bp + (size_t)row * K + pt * BK + c * 4);
        }
        asm volatile("cp.async.commit_group;" ::: "memory");
    }

    for (int kt = 0; kt < KT; kt++) {
        cp_wait<NSTG - 2>();
        __syncthreads();
        const float* As = smem + (kt % NSTG) * STAGE_FLOATS;
        const float* Bs = As + BM * BKP;

#pragma unroll
        for (int k8 = 0; k8 < BK / 8; k8++) {
            int k0 = k8 * 8;
            uint32_t af[4][4], bf[4][2];
#pragma unroll
            for (int mf = 0; mf < 4; mf++) {
                const float* p = As + (wm * 64 + mf * 16 + grp) * BKP + k0 + tig;
                af[mf][0] = __float_as_uint(p[0]);
                af[mf][1] = __float_as_uint(p[8 * BKP]);
                af[mf][2] = __float_as_uint(p[4]);
                af[mf][3] = __float_as_uint(p[8 * BKP + 4]);
            }
#pragma unroll
            for (int nf = 0; nf < 4; nf++) {
                const float* p = Bs + (wn * 32 + nf * 8 + grp) * BKP + k0 + tig;
                bf[nf][0] = __float_as_uint(p[0]);
                bf[nf][1] = __float_as_uint(p[4]);
            }
#pragma unroll
            for (int mf = 0; mf < 4; mf++)
#pragma unroll
                for (int nf = 0; nf < 4; nf++)
                    asm volatile(
                        "mma.sync.aligned.m16n8k8.row.col.f32.tf32.tf32.f32 "
                        "{%0,%1,%2,%3}, {%4,%5,%6,%7}, {%8,%9}, {%0,%1,%2,%3};"
                        : "+f"(acc[mf][nf][0]), "+f"(acc[mf][nf][1]),
                          "+f"(acc[mf][nf][2]), "+f"(acc[mf][nf][3])
                        : "r"(af[mf][0]), "r"(af[mf][1]),
                          "r"(af[mf][2]), "r"(af[mf][3]),
                          "r"(bf[nf][0]), "r"(bf[nf][1]));
        }
        __syncthreads();

        int lt = kt + NSTG - 1;
        if (lt < KT) {
            float* dstA = smem + (lt % NSTG) * STAGE_FLOATS;
            float* dstB = dstA + BM * BKP;
#pragma unroll
            for (int i = 0; i < 4; i++) {
                int idx = tid + i * 256, row = idx >> 3, c = idx & 7;
                cp_async16(smem_u32(dstA + row * BKP + c * 4),
                           Ap + (size_t)row * K + lt * BK + c * 4);
            }
#pragma unroll
            for (int i = 0; i < 4; i++) {
                int idx = tid + i * 256, row = idx >> 3, c = idx & 7;
                cp_async16(smem_u32(dstB + row * BKP + c * 4),
                           Bp + (size_t)row * K + lt * BK + c * 4);
            }
            asm volatile("cp.async.commit_group;" ::: "memory");
        }
    }

    // epilogue
    int rowBase = blockIdx.y * BM, colBase = blockIdx.x * BN;
#pragma unroll
    for (int mf = 0; mf < 4; mf++) {
        int r0 = rowBase + wm * 64 + mf * 16 + grp;
        float s0 = mode ? rs[r0] : 1.f;
        float s1 = mode ? rs[r0 + 8] : 1.f;
#pragma unroll
        for (int nf = 0; nf < 4; nf++) {
            int col = colBase + wn * 32 + nf * 8 + tig * 2;
            float2 v0 = { acc[mf][nf][0] * s0, acc[mf][nf][1] * s0 };
            float2 v1 = { acc[mf][nf][2] * s1, acc[mf][nf][3] * s1 };
            *(float2*)(Cp + (size_t)r0 * N + col) = v0;
            *(float2*)(Cp + (size_t)(r0 + 8) * N + col) = v1;
        }
    }
}

// ----------------- silu(g)*u elementwise, rounded to tf32 -------------------
__global__ __launch_bounds__(256) void silu_mul_kernel(
    const float* __restrict__ g, const float* __restrict__ u,
    float* __restrict__ h, int n4)
{
    int i = blockIdx.x * blockDim.x + threadIdx.x;
    if (i >= n4) return;
    float4 gv = ((const float4*)g)[i];
    float4 uv = ((const float4*)u)[i];
    float4 r;
    r.x = rna_tf32(gv.x / (1.f + expf(-gv.x)) * uv.x);
    r.y = rna_tf32(gv.y / (1.f + expf(-gv.y)) * uv.y);
    r.z = rna_tf32(gv.z / (1.f + expf(-gv.z)) * uv.z);
    r.w = rna_tf32(gv.w / (1.f + expf(-gv.w)) * uv.w);
    ((float4*)h)[i] = r;
}

// ----------------- combine dyn expert outputs into out ----------------------
__global__ __launch_bounds__(256) void combine_kernel(float* __restrict__ out)
{
    int t = blockIdx.x;
    int c = threadIdx.x;
    float4 acc = ((float4*)(out + (size_t)t * HD))[c];
#pragma unroll
    for (int k = 0; k < TOPK; k++) {
        int pos = d_tokpos[t * TOPK + k];
        if (pos >= 0) {
            int e = d_toke[t * TOPK + k];
            float w = d_tokw[t * TOPK + k];
            float4 v = ((const float4*)(d_ybuf + ((size_t)e * CAPV + pos) * HD))[c];
            acc.x += w * v.x; acc.y += w * v.y;
            acc.z += w * v.z; acc.w += w * v.w;
        }
    }
    ((float4*)(out + (size_t)t * HD))[c] = acc;
}

// ----------------- host launcher --------------------------------------------
extern "C" void kernel_launch(void* const* d_in, const int* in_sizes, int n_in,
                              void* d_out, int out_size)
{
    const float* x   = (const float*)d_in[0];
    const float* gw  = (const float*)d_in[1];
    const float* dgw = (const float*)d_in[2];
    const float* duw = (const float*)d_in[3];
    const float* ddw = (const float*)d_in[4];
    const float* sgw = (const float*)d_in[5];
    const float* suw = (const float*)d_in[6];
    const float* sdw = (const float*)d_in[7];
    float* out = (float*)d_out;

    float *p_xe, *p_g, *p_u, *p_h, *p_y, *p_gs, *p_us, *p_hs, *p_wsh, *p_xr;
    float *p_dgw, *p_duw, *p_ddw, *p_sgw, *p_suw, *p_sdw;
    cudaGetSymbolAddress((void**)&p_xe, d_xe);
    cudaGetSymbolAddress((void**)&p_g, d_gbuf);
    cudaGetSymbolAddress((void**)&p_u, d_ubuf);
    cudaGetSymbolAddress((void**)&p_h, d_hbuf);
    cudaGetSymbolAddress((void**)&p_y, d_ybuf);
    cudaGetSymbolAddress((void**)&p_gs, d_gs);
    cudaGetSymbolAddress((void**)&p_us, d_us);
    cudaGetSymbolAddress((void**)&p_hs, d_hs);
    cudaGetSymbolAddress((void**)&p_wsh, d_wsh);
    cudaGetSymbolAddress((void**)&p_xr, d_xr);
    cudaGetSymbolAddress((void**)&p_dgw, d_dgw_r);
    cudaGetSymbolAddress((void**)&p_duw, d_duw_r);
    cudaGetSymbolAddress((void**)&p_ddw, d_ddw_r);
    cudaGetSymbolAddress((void**)&p_sgw, d_sgw_r);
    cudaGetSymbolAddress((void**)&p_suw, d_suw_r);
    cudaGetSymbolAddress((void**)&p_sdw, d_sdw_r);

    cudaFuncSetAttribute(tf32_gemm_kernel,
                         cudaFuncAttributeMaxDynamicSharedMemorySize, GEMM_SMEM);

    // tf32 rounding prepass
    int nDW = EDN * IDY * HD / 4, nSW = IFX * HD / 4, nX = TT * HD / 4;
    round_kernel<<<(nDW + 255) / 256, 256>>>((const float4*)dgw, (float4*)p_dgw, nDW);
    round_kernel<<<(nDW + 255) / 256, 256>>>((const float4*)duw, (float4*)p_duw, nDW);
    round_kernel<<<(nDW + 255) / 256, 256>>>((const float4*)ddw, (float4*)p_ddw, nDW);
    round_kernel<<<(nSW + 255) / 256, 256>>>((const float4*)sgw, (float4*)p_sgw, nSW);
    round_kernel<<<(nSW + 255) / 256, 256>>>((const float4*)suw, (float4*)p_suw, nSW);
    round_kernel<<<(nSW + 255) / 256, 256>>>((const float4*)sdw, (float4*)p_sdw, nSW);
    round_kernel<<<(nX + 255) / 256, 256>>>((const float4*)x, (float4*)p_xr, nX);

    // routing
    logits_kernel<<<(TT * NE + 7) / 8, 256>>>(x, gw);
    routing_kernel<<<(TT + 255) / 256, 256>>>();
    scan_kernel<<<EDN, 1024>>>();
    init_counts_kernel<<<1, 32>>>();
    finalize_kernel<<<(TT + 255) / 256, 256>>>();
    gather_kernel<<<EDN * CAPV, 256>>>(x);

    // dyn experts: fused gate+up launch (z<8: gate, z>=8: up)
    dim3 gd1(IDY / BN, CAPV / BM, 2 * EDN);
    tf32_gemm_kernel<<<gd1, 256, GEMM_SMEM>>>(
        p_xe, p_dgw, p_duw, p_g, p_u, HD, IDY,
        (size_t)CAPV * HD, (size_t)IDY * HD, (size_t)CAPV * IDY, EDN, 0, nullptr);
    int n4d = EDN * CAPV * IDY / 4;
    silu_mul_kernel<<<(n4d + 255) / 256, 256>>>(p_g, p_u, p_h, n4d);
    dim3 gd2(HD / BN, CAPV / BM, EDN);
    tf32_gemm_kernel<<<gd2, 256, GEMM_SMEM>>>(
        p_h, p_ddw, nullptr, p_y, nullptr, IDY, HD,
        (size_t)CAPV * IDY, (size_t)HD * IDY, (size_t)CAPV * HD, EDN, 0, nullptr);

    // shared expert: fused gate+up (z=0: gate, z=1: up)
    dim3 gs1(IFX / BN, TT / BM, 2);
    tf32_gemm_kernel<<<gs1, 256, GEMM_SMEM>>>(
        p_xr, p_sgw, p_suw, p_gs, p_us, HD, IFX, 0, 0, 0, 1, 0, nullptr);
    int n4s = TT * IFX / 4;
    silu_mul_kernel<<<(n4s + 255) / 256, 256>>>(p_gs, p_us, p_hs, n4s);
    dim3 gs2(HD / BN, TT / BM, 1);
    tf32_gemm_kernel<<<gs2, 256, GEMM_SMEM>>>(
        p_hs, p_sdw, nullptr, out, nullptr, IFX, HD, 0, 0, 0, 1, 1, p_wsh);

    // add dyn contributions
    combine_kernel<<<TT, 256>>>(out);
}